// round 15
// baseline (speedup 1.0000x reference)
#include <cuda_runtime.h>
#include <cuda_bf16.h>
#include <stdint.h>
#include <math.h>
#include <stddef.h>

// Problem constants (fixed by the reference: B=32, T=D=256)
#define BB 32
#define TT 256
#define DD 256
#define EPSF 1e-18f
#define NCHUNK 8

// -------- scratch (device globals; no allocation allowed) --------
__device__ float g_part[2 * BB * NCHUNK * TT];   // [(isA*32+i)*8+chunk][s]
__device__ __align__(16) unsigned short g_VFb[BB * TT * DD];
__device__ __align__(16) unsigned short g_AFb[BB * TT * DD];
// Folded B operands: Bd1[i,s,d] = R1[s,d]-w1[i,s]*AF[i,s,d], Bd2 likewise with V
__device__ __align__(16) unsigned short g_Bd1[BB * TT * DD];
__device__ __align__(16) unsigned short g_Bd2[BB * TT * DD];

__device__ __forceinline__ uint32_t smem_u32(const void* p) {
    uint32_t r;
    asm("{ .reg .u64 t; cvta.to.shared.u64 t, %1; cvt.u32.u64 %0, t; }"
        : "=r"(r) : "l"(p));
    return r;
}

// ============================================================
// Kernel 1: partial col sums of squares + bf16 convert.
// __launch_bounds__(256, 4) -> 64-reg budget so ptxas can hold v[8]
// in registers: 8 outstanding LDG.128 per thread (true MLP=8).
// grid = 512 (isA(2) x i(32) x chunk(8)), 256 threads.
// ============================================================
__global__ void __launch_bounds__(256, 4)
stats1_kernel(const float* __restrict__ VF,
              const float* __restrict__ AF) {
    const int chunk = blockIdx.x & 7;
    const int i     = (blockIdx.x >> 3) & 31;
    const int isA   = blockIdx.x >> 8;
    const float* X = isA ? AF : VF;
    unsigned short* Xb = isA ? g_AFb : g_VFb;

    const int tid = threadIdx.x;
    const int c4  = (tid & 63) * 4;   // column quad
    const int rg  = tid >> 6;         // row group 0..3

    const size_t rowbase = ((size_t)i * TT + chunk * 32 + rg * 8) * DD + c4;

    // batch all loads first -> 8 outstanding LDG.128
    float4 v[8];
#pragma unroll
    for (int r = 0; r < 8; ++r)
        v[r] = *(const float4*)(X + rowbase + (size_t)r * DD);

    float a0 = 0.f, a1 = 0.f, a2 = 0.f, a3 = 0.f;
#pragma unroll
    for (int r = 0; r < 8; ++r) {
        a0 += v[r].x * v[r].x; a1 += v[r].y * v[r].y;
        a2 += v[r].z * v[r].z; a3 += v[r].w * v[r].w;
        __nv_bfloat162 lo = __float22bfloat162_rn(make_float2(v[r].x, v[r].y));
        __nv_bfloat162 hi = __float22bfloat162_rn(make_float2(v[r].z, v[r].w));
        uint2 packed;
        packed.x = *(uint32_t*)&lo;
        packed.y = *(uint32_t*)&hi;
        *(uint2*)(Xb + rowbase + (size_t)r * DD) = packed;
    }

    __shared__ float sh[4 * 256];
    sh[rg * 256 + c4 + 0] = a0;
    sh[rg * 256 + c4 + 1] = a1;
    sh[rg * 256 + c4 + 2] = a2;
    sh[rg * 256 + c4 + 3] = a3;
    __syncthreads();

    const int c = tid;
    float part = sh[c] + sh[256 + c] + sh[512 + c] + sh[768 + c];
    g_part[((size_t)((isA * BB + i) * NCHUNK + chunk)) * TT + c] = part;
}

// ============================================================
// Kernel 2 (frozen): recompute w[j,s] from g_part, fold into Bd matrices.
// ============================================================
__global__ void build_kernel() {
    const int s   = blockIdx.x;
    const int dir = blockIdx.y;   // 0: AF/w1 -> Bd1, 1: VF/w2 -> Bd2
    const int d   = threadIdx.x;
    const unsigned short* X = dir ? g_VFb : g_AFb;
    unsigned short* Bd = dir ? g_Bd2 : g_Bd1;
    const int isA = dir ? 0 : 1;

    __shared__ float sw[BB];
    if (d < BB) {
        const float* p = g_part + ((size_t)((isA * BB + d) * NCHUNK)) * TT + s;
        float acc = 0.f;
#pragma unroll
        for (int c = 0; c < NCHUNK; ++c) acc += p[c * TT];
        sw[d] = rsqrtf(acc + EPSF);
    }
    __syncthreads();

    float xv[BB];
    float R = 0.f;
#pragma unroll
    for (int j = 0; j < BB; ++j) {
        xv[j] = __bfloat162float(__ushort_as_bfloat16(X[((size_t)j * TT + s) * DD + d]));
        R += sw[j] * xv[j];
    }
#pragma unroll
    for (int j = 0; j < BB; ++j) {
        float v = R - sw[j] * xv[j];
        Bd[((size_t)j * TT + s) * DD + d] = __bfloat16_as_ushort(__float2bfloat16(v));
    }
}

// ============================================================
// Kernel 3 (R11 winner, frozen): HMMA dual-GEMM, 1024 threads (32 warps 4x8),
//   warp tile 32(M)x16(N) per GEMM, BK=64 (4 k-tiles), 3-stage cp.async.
//   vi1/vi2 computed in-kernel from g_part (hidden under prologue loads).
// grid = 2 x 2 x 32 = 128 CTAs -> single wave, 1 CTA(32 warps)/SM.
// ============================================================
#define LDE 72                            // smem row stride in bf16 (144B)
#define TILE_B (128 * LDE * 2)            // 18432 B per operand tile
#define STAGE_BYTES (4 * TILE_B)          // 73728 B (V, A, Bd1, Bd2)
#define STAGES 3
#define SMEM_BYTES (STAGES * STAGE_BYTES) // 221184

__device__ __forceinline__ void ldsm4(uint32_t* r, uint32_t addr) {
    asm volatile("ldmatrix.sync.aligned.m8n8.x4.shared.b16 {%0,%1,%2,%3}, [%4];"
                 : "=r"(r[0]), "=r"(r[1]), "=r"(r[2]), "=r"(r[3]) : "r"(addr));
}

__device__ __forceinline__ void mma_bf16(float* c, const uint32_t* a, const uint32_t* b) {
    asm volatile("mma.sync.aligned.m16n8k16.row.col.f32.bf16.bf16.f32 "
                 "{%0,%1,%2,%3},{%4,%5,%6,%7},{%8,%9},{%0,%1,%2,%3};"
                 : "+f"(c[0]), "+f"(c[1]), "+f"(c[2]), "+f"(c[3])
                 : "r"(a[0]), "r"(a[1]), "r"(a[2]), "r"(a[3]),
                   "r"(b[0]), "r"(b[1]));
}

__device__ __forceinline__ void cpa16(uint32_t dst, const void* src) {
    asm volatile("cp.async.cg.shared.global [%0], [%1], 16;\n"
                 :: "r"(dst), "l"(src) : "memory");
}

__device__ __forceinline__ float lg1p(float x) {
    if (fabsf(x) < 0.0625f)
        return x * fmaf(x, fmaf(x, fmaf(x, -0.25f, 0.33333333333f), -0.5f), 1.0f);
    return log1pf(x);
}

__global__ void __launch_bounds__(1024, 1)
main_kernel(float* __restrict__ out) {
    extern __shared__ unsigned short dynsmem[];
    __shared__ float redA[32], redB[32];
    const uint32_t sbase = smem_u32(dynsmem);

    const int i  = blockIdx.z;
    const int t0 = blockIdx.y * 128;
    const int s0 = blockIdx.x * 128;

    const int tid  = threadIdx.x;
    const int lane = tid & 31;
    const int wid  = tid >> 5;   // 0..31
    const int wm   = wid & 3;    // warp row (t): 4 x 32 rows
    const int wn   = wid >> 2;   // warp col (s): 8 x 16 cols

    // cp.async mapping: row = tid>>3 (0..127), one 16B chunk at (tid&7)*8
    const int row = tid >> 3;
    const int c8  = (tid & 7) * 8;

    const unsigned short* pV  = g_VFb + ((size_t)(i * TT + t0 + row)) * DD + c8;
    const unsigned short* pA  = g_AFb + ((size_t)(i * TT + t0 + row)) * DD + c8;
    const unsigned short* pB1 = g_Bd1 + ((size_t)(i * TT + s0 + row)) * DD + c8;
    const unsigned short* pB2 = g_Bd2 + ((size_t)(i * TT + s0 + row)) * DD + c8;

    const uint32_t so = (uint32_t)((row * LDE + c8) * 2);

    // warp tile 32x16 per GEMM: acc[mf(2)][n8(2)][4] x 2 GEMMs = 32 regs
    float acc1[2][2][4] = {};
    float acc2[2][2][4] = {};

    const uint32_t arel = (uint32_t)(((wm * 32 + (lane & 15)) * LDE + ((lane >> 4) * 8)) * 2);
    const uint32_t brel = (uint32_t)(((wn * 16 + (lane & 7) + ((lane & 16) >> 1)) * LDE
                                      + (((lane >> 3) & 1) * 8)) * 2);

#define ISSUE_STAGE(buf, k)                                                    \
    do {                                                                       \
        const uint32_t b_ = sbase + (uint32_t)(buf) * STAGE_BYTES;             \
        const int ko_ = (k) * 64;                                              \
        cpa16(b_ + 0 * TILE_B + so, pV + ko_);                                 \
        cpa16(b_ + 1 * TILE_B + so, pA + ko_);                                 \
        cpa16(b_ + 2 * TILE_B + so, pB1 + ko_);                                \
        cpa16(b_ + 3 * TILE_B + so, pB2 + ko_);                                \
        asm volatile("cp.async.commit_group;\n" ::: "memory");                 \
    } while (0)

    ISSUE_STAGE(0, 0);
    ISSUE_STAGE(1, 1);

    // ---- vi1/vi2 partial reduce from g_part (hides under tile-0 flight) ----
    {
        const float* q1 = g_part + (size_t)i * (NCHUNK * TT);
        const float* q2 = g_part + (size_t)(BB + i) * (NCHUNK * TT);
        float p1 = q1[tid] + q1[tid + 1024];
        float p2 = q2[tid] + q2[tid + 1024];
#pragma unroll
        for (int o = 16; o > 0; o >>= 1) {
            p1 += __shfl_xor_sync(0xFFFFFFFFu, p1, o);
            p2 += __shfl_xor_sync(0xFFFFFFFFu, p2, o);
        }
        if (lane == 0) { redA[wid] = p1; redB[wid] = p2; }
    }

#pragma unroll
    for (int k0 = 0; k0 < 4; ++k0) {
        asm volatile("cp.async.wait_group 1;\n" ::: "memory");
        __syncthreads();

        if (k0 + 2 < 4) {
            ISSUE_STAGE((k0 + 2) % STAGES, k0 + 2);
        } else {
            asm volatile("cp.async.commit_group;\n" ::: "memory");
        }

        const uint32_t bV  = sbase + (uint32_t)((k0 % STAGES)) * STAGE_BYTES;
        const uint32_t bA  = bV + 1 * TILE_B;
        const uint32_t bB1 = bV + 2 * TILE_B;
        const uint32_t bB2 = bV + 3 * TILE_B;

#pragma unroll
        for (int ks = 0; ks < 4; ++ks) {
            uint32_t av[2][4], aa[2][4];
            uint32_t b1[4], b2[4];
#pragma unroll
            for (int mf = 0; mf < 2; ++mf) {
                const uint32_t ao = (uint32_t)((mf * 16 * LDE + ks * 16) * 2);
                ldsm4(av[mf], bV + arel + ao);
                ldsm4(aa[mf], bA + arel + ao);
            }
            {
                const uint32_t bo = (uint32_t)((ks * 16) * 2);
                ldsm4(b1, bB1 + brel + bo);
                ldsm4(b2, bB2 + brel + bo);
            }
#pragma unroll
            for (int mf = 0; mf < 2; ++mf) {
                mma_bf16(acc1[mf][0], av[mf], &b1[0]);
                mma_bf16(acc1[mf][1], av[mf], &b1[2]);
                mma_bf16(acc2[mf][0], aa[mf], &b2[0]);
                mma_bf16(acc2[mf][1], aa[mf], &b2[2]);
            }
        }
    }

    // ---- finalize vi ----
    __syncthreads();
    float s1 = 0.f, s2 = 0.f;
#pragma unroll
    for (int w = 0; w < 32; ++w) { s1 += redA[w]; s2 += redB[w]; }
    const float vi1 = rsqrtf(s1 + EPSF);
    const float vi2 = rsqrtf(s2 + EPSF);

    // ---- epilogue ----
    const float INV32 = 1.0f / 32.0f;
    const float TWO_LN32 = 6.931471805599453f;

#pragma unroll
    for (int mf = 0; mf < 2; ++mf) {
        const int rbase = t0 + wm * 32 + mf * 16 + (lane >> 2);
#pragma unroll
        for (int n8 = 0; n8 < 2; ++n8) {
            const int col = s0 + wn * 16 + n8 * 8 + (lane & 3) * 2;
            const float* c1 = acc1[mf][n8];
            const float* c2 = acc2[mf][n8];
            float2 o0, o1;
            o0.x = -(TWO_LN32 + lg1p(vi1 * c1[0] * INV32) + lg1p(vi2 * c2[0] * INV32));
            o0.y = -(TWO_LN32 + lg1p(vi1 * c1[1] * INV32) + lg1p(vi2 * c2[1] * INV32));
            o1.x = -(TWO_LN32 + lg1p(vi1 * c1[2] * INV32) + lg1p(vi2 * c2[2] * INV32));
            o1.y = -(TWO_LN32 + lg1p(vi1 * c1[3] * INV32) + lg1p(vi2 * c2[3] * INV32));
            *(float2*)&out[((size_t)(i * TT + rbase)) * TT + col] = o0;
            *(float2*)&out[((size_t)(i * TT + rbase + 8)) * TT + col] = o1;
        }
    }
}

// ============================================================
extern "C" void kernel_launch(void* const* d_in, const int* in_sizes, int n_in,
                              void* d_out, int out_size) {
    // metadata order: pre_VF, pre_AF, back_VF, back_AF (only back_* are used)
    const float* VF = (const float*)d_in[2];
    const float* AF = (const float*)d_in[3];
    float* out = (float*)d_out;
    (void)in_sizes; (void)n_in; (void)out_size;

    cudaFuncSetAttribute(main_kernel,
                         cudaFuncAttributeMaxDynamicSharedMemorySize, SMEM_BYTES);

    stats1_kernel<<<512, 256>>>(VF, AF);
    build_kernel<<<dim3(256, 2), 256>>>();
    main_kernel<<<dim3(2, 2, 32), 1024, SMEM_BYTES>>>(out);
}

// round 16
// speedup vs baseline: 1.1015x; 1.1015x over previous
#include <cuda_runtime.h>
#include <cuda_bf16.h>
#include <stdint.h>
#include <math.h>
#include <stddef.h>

// Problem constants (fixed by the reference: B=32, T=D=256)
#define BB 32
#define TT 256
#define DD 256
#define EPSF 1e-18f
#define NCHUNK 8

// -------- scratch (device globals; no allocation allowed) --------
__device__ float g_part[2 * BB * NCHUNK * TT];   // [(isA*32+i)*8+chunk][s]
__device__ __align__(16) unsigned char g_V8[BB * TT * DD];   // e4m3 copy of back_VF
__device__ __align__(16) unsigned char g_A8[BB * TT * DD];   // e4m3 copy of back_AF
// Folded B operands (e4m3): Bd1[i,s,d] = R1[s,d]-w1[i,s]*AF[i,s,d]; Bd2 with V
__device__ __align__(16) unsigned char g_B18[BB * TT * DD];
__device__ __align__(16) unsigned char g_B28[BB * TT * DD];

__device__ __forceinline__ uint32_t smem_u32(const void* p) {
    uint32_t r;
    asm("{ .reg .u64 t; cvta.to.shared.u64 t, %1; cvt.u32.u64 %0, t; }"
        : "=r"(r) : "l"(p));
    return r;
}

// pack float4 -> 4 x e4m3 bytes (x in lowest byte)
__device__ __forceinline__ uint32_t pack_e4m3(float4 v) {
    uint16_t h1, h2;
    asm("cvt.rn.satfinite.e4m3x2.f32 %0, %1, %2;" : "=h"(h1) : "f"(v.y), "f"(v.x));
    asm("cvt.rn.satfinite.e4m3x2.f32 %0, %1, %2;" : "=h"(h2) : "f"(v.w), "f"(v.z));
    return (uint32_t)h1 | ((uint32_t)h2 << 16);
}

// ============================================================
// Kernel 1: partial col sums of squares (fp32 exact) + e4m3 convert.
// grid = 512 (isA(2) x i(32) x chunk(8)), 256 threads.
// ============================================================
__global__ void __launch_bounds__(256)
stats1_kernel(const float* __restrict__ VF,
              const float* __restrict__ AF) {
    const int chunk = blockIdx.x & 7;
    const int i     = (blockIdx.x >> 3) & 31;
    const int isA   = blockIdx.x >> 8;
    const float* X = isA ? AF : VF;
    unsigned char* X8 = isA ? g_A8 : g_V8;

    const int tid = threadIdx.x;
    const int c4  = (tid & 63) * 4;   // column quad
    const int rg  = tid >> 6;         // row group 0..3

    const size_t rowbase = ((size_t)i * TT + chunk * 32 + rg * 8) * DD + c4;

    float a0 = 0.f, a1 = 0.f, a2 = 0.f, a3 = 0.f;
#pragma unroll
    for (int r = 0; r < 8; ++r) {
        float4 v = *(const float4*)(X + rowbase + (size_t)r * DD);
        a0 += v.x * v.x; a1 += v.y * v.y; a2 += v.z * v.z; a3 += v.w * v.w;
        *(uint32_t*)(X8 + rowbase + (size_t)r * DD) = pack_e4m3(v);
    }

    __shared__ float sh[4 * 256];
    sh[rg * 256 + c4 + 0] = a0;
    sh[rg * 256 + c4 + 1] = a1;
    sh[rg * 256 + c4 + 2] = a2;
    sh[rg * 256 + c4 + 3] = a3;
    __syncthreads();

    const int c = tid;
    float part = sh[c] + sh[256 + c] + sh[512 + c] + sh[768 + c];
    g_part[((size_t)((isA * BB + i) * NCHUNK + chunk)) * TT + c] = part;
}

// ============================================================
// Kernel 2: compute w[j,s] from g_part, fold j-sum + per-i correction,
// emit e4m3 Bd. Reads fp32 originals (single quantization of Bd).
// grid (256 s, 2 dir), 256 threads: (jg = tid>>6 owns 8 j's) x (d4 quad).
// ============================================================
__global__ void build_kernel(const float* __restrict__ VF,
                             const float* __restrict__ AF) {
    const int s   = blockIdx.x;
    const int dir = blockIdx.y;   // 0: AF/w1 -> Bd1, 1: VF/w2 -> Bd2
    const float* X = dir ? VF : AF;
    unsigned char* Bd = dir ? g_B28 : g_B18;
    const int isA = dir ? 0 : 1;

    const int tid = threadIdx.x;
    const int jg  = tid >> 6;          // 0..3 (owns j = jg*8 .. +7)
    const int d4  = (tid & 63) * 4;    // column quad

    __shared__ float sw[BB];
    __shared__ float pR[4][256];
    if (tid < BB) {
        const float* p = g_part + ((size_t)((isA * BB + tid) * NCHUNK)) * TT + s;
        float acc = 0.f;
#pragma unroll
        for (int c = 0; c < NCHUNK; ++c) acc += p[c * TT];
        sw[tid] = rsqrtf(acc + EPSF);
    }
    __syncthreads();

    float4 xv[8];
    float4 R = make_float4(0.f, 0.f, 0.f, 0.f);
#pragma unroll
    for (int jj = 0; jj < 8; ++jj) {
        const int j = jg * 8 + jj;
        xv[jj] = *(const float4*)(X + ((size_t)j * TT + s) * DD + d4);
        const float w = sw[j];
        R.x += w * xv[jj].x; R.y += w * xv[jj].y;
        R.z += w * xv[jj].z; R.w += w * xv[jj].w;
    }
    *(float4*)&pR[jg][d4] = R;
    __syncthreads();

    float4 Rt;
    {
        float4 r0 = *(const float4*)&pR[0][d4];
        float4 r1 = *(const float4*)&pR[1][d4];
        float4 r2 = *(const float4*)&pR[2][d4];
        float4 r3 = *(const float4*)&pR[3][d4];
        Rt.x = r0.x + r1.x + r2.x + r3.x;
        Rt.y = r0.y + r1.y + r2.y + r3.y;
        Rt.z = r0.z + r1.z + r2.z + r3.z;
        Rt.w = r0.w + r1.w + r2.w + r3.w;
    }
#pragma unroll
    for (int jj = 0; jj < 8; ++jj) {
        const int j = jg * 8 + jj;
        const float w = sw[j];
        float4 b;
        b.x = Rt.x - w * xv[jj].x; b.y = Rt.y - w * xv[jj].y;
        b.z = Rt.z - w * xv[jj].z; b.w = Rt.w - w * xv[jj].w;
        *(uint32_t*)(Bd + ((size_t)j * TT + s) * DD + d4) = pack_e4m3(b);
    }
}

// ============================================================
// Kernel 3: fp8 HMMA dual-GEMM (m16n8k32 e4m3), 1024 threads (32 warps 4x8),
//   warp tile 32(M)x16(N) per GEMM, 2 k-chunks of 128 fp8, 2-stage cp.async.
//   vi1/vi2 computed in-kernel from g_part.
// grid = 2 x 2 x 32 = 128 CTAs -> single wave, 1 CTA/SM.
// ============================================================
#define LDEB 144                          // smem row stride in BYTES
#define TILE_B (128 * LDEB)               // 18432 B per operand tile
#define STAGE_BYTES (4 * TILE_B)          // 73728 B (V, A, Bd1, Bd2)
#define SMEM_BYTES (2 * STAGE_BYTES)      // 147456

__device__ __forceinline__ void ldsm4(uint32_t* r, uint32_t addr) {
    asm volatile("ldmatrix.sync.aligned.m8n8.x4.shared.b16 {%0,%1,%2,%3}, [%4];"
                 : "=r"(r[0]), "=r"(r[1]), "=r"(r[2]), "=r"(r[3]) : "r"(addr));
}

__device__ __forceinline__ void mma_fp8(float* c, const uint32_t* a, const uint32_t* b) {
    asm volatile("mma.sync.aligned.m16n8k32.row.col.f32.e4m3.e4m3.f32 "
                 "{%0,%1,%2,%3},{%4,%5,%6,%7},{%8,%9},{%0,%1,%2,%3};"
                 : "+f"(c[0]), "+f"(c[1]), "+f"(c[2]), "+f"(c[3])
                 : "r"(a[0]), "r"(a[1]), "r"(a[2]), "r"(a[3]),
                   "r"(b[0]), "r"(b[1]));
}

__device__ __forceinline__ void cpa16(uint32_t dst, const void* src) {
    asm volatile("cp.async.cg.shared.global [%0], [%1], 16;\n"
                 :: "r"(dst), "l"(src) : "memory");
}

__device__ __forceinline__ float lg1p(float x) {
    if (fabsf(x) < 0.0625f)
        return x * fmaf(x, fmaf(x, fmaf(x, -0.25f, 0.33333333333f), -0.5f), 1.0f);
    return log1pf(x);
}

__global__ void __launch_bounds__(1024, 1)
main_kernel(float* __restrict__ out) {
    extern __shared__ unsigned char dynsmem[];
    __shared__ float redA[32], redB[32];
    const uint32_t sbase = smem_u32(dynsmem);

    const int i  = blockIdx.z;
    const int t0 = blockIdx.y * 128;
    const int s0 = blockIdx.x * 128;

    const int tid  = threadIdx.x;
    const int lane = tid & 31;
    const int wid  = tid >> 5;   // 0..31
    const int wm   = wid & 3;    // warp row (t): 4 x 32 rows
    const int wn   = wid >> 2;   // warp col (s): 8 x 16 cols

    // cp.async mapping: row = tid>>3 (0..127), one 16B chunk at (tid&7)*16
    const int row = tid >> 3;
    const int cB  = (tid & 7) * 16;   // byte offset within 128B chunk

    const unsigned char* pV  = g_V8  + ((size_t)(i * TT + t0 + row)) * DD + cB;
    const unsigned char* pA  = g_A8  + ((size_t)(i * TT + t0 + row)) * DD + cB;
    const unsigned char* pB1 = g_B18 + ((size_t)(i * TT + s0 + row)) * DD + cB;
    const unsigned char* pB2 = g_B28 + ((size_t)(i * TT + s0 + row)) * DD + cB;

    const uint32_t so = (uint32_t)(row * LDEB + cB);

    // warp tile 32x16 per GEMM: acc[mf(2)][n8(2)][4] x 2 GEMMs = 32 regs
    float acc1[2][2][4] = {};
    float acc2[2][2][4] = {};

    // ldsm per-thread relative BYTE offsets within an operand tile
    const uint32_t arel = (uint32_t)((wm * 32 + (lane & 15)) * LDEB + (lane >> 4) * 16);
    const uint32_t brel = (uint32_t)((wn * 16 + (lane & 7) + ((lane & 16) >> 1)) * LDEB
                                     + ((lane >> 3) & 1) * 16);

#define ISSUE_STAGE(buf, k)                                                    \
    do {                                                                       \
        const uint32_t b_ = sbase + (uint32_t)(buf) * STAGE_BYTES;             \
        const int ko_ = (k) * 128;                                             \
        cpa16(b_ + 0 * TILE_B + so, pV + ko_);                                 \
        cpa16(b_ + 1 * TILE_B + so, pA + ko_);                                 \
        cpa16(b_ + 2 * TILE_B + so, pB1 + ko_);                                \
        cpa16(b_ + 3 * TILE_B + so, pB2 + ko_);                                \
        asm volatile("cp.async.commit_group;\n" ::: "memory");                 \
    } while (0)

    ISSUE_STAGE(0, 0);
    ISSUE_STAGE(1, 1);

    // ---- vi1/vi2 partial reduce from g_part (hides under tile-0 flight) ----
    {
        const float* q1 = g_part + (size_t)i * (NCHUNK * TT);
        const float* q2 = g_part + (size_t)(BB + i) * (NCHUNK * TT);
        float p1 = q1[tid] + q1[tid + 1024];
        float p2 = q2[tid] + q2[tid + 1024];
#pragma unroll
        for (int o = 16; o > 0; o >>= 1) {
            p1 += __shfl_xor_sync(0xFFFFFFFFu, p1, o);
            p2 += __shfl_xor_sync(0xFFFFFFFFu, p2, o);
        }
        if (lane == 0) { redA[wid] = p1; redB[wid] = p2; }
    }

#pragma unroll
    for (int k0 = 0; k0 < 2; ++k0) {
        if (k0 == 0) {
            asm volatile("cp.async.wait_group 1;\n" ::: "memory");
        } else {
            asm volatile("cp.async.wait_group 0;\n" ::: "memory");
        }
        __syncthreads();

        const uint32_t bV  = sbase + (uint32_t)k0 * STAGE_BYTES;
        const uint32_t bA  = bV + 1 * TILE_B;
        const uint32_t bB1 = bV + 2 * TILE_B;
        const uint32_t bB2 = bV + 3 * TILE_B;

#pragma unroll
        for (int ks = 0; ks < 4; ++ks) {
            uint32_t av[2][4], aa[2][4];
            uint32_t b1[4], b2[4];
#pragma unroll
            for (int mf = 0; mf < 2; ++mf) {
                const uint32_t ao = (uint32_t)(mf * 16 * LDEB + ks * 32);
                ldsm4(av[mf], bV + arel + ao);
                ldsm4(aa[mf], bA + arel + ao);
            }
            {
                const uint32_t bo = (uint32_t)(ks * 32);
                ldsm4(b1, bB1 + brel + bo);
                ldsm4(b2, bB2 + brel + bo);
            }
#pragma unroll
            for (int mf = 0; mf < 2; ++mf) {
                mma_fp8(acc1[mf][0], av[mf], &b1[0]);
                mma_fp8(acc1[mf][1], av[mf], &b1[2]);
                mma_fp8(acc2[mf][0], aa[mf], &b2[0]);
                mma_fp8(acc2[mf][1], aa[mf], &b2[2]);
            }
        }
    }

    // ---- finalize vi ----
    __syncthreads();
    float s1 = 0.f, s2 = 0.f;
#pragma unroll
    for (int w = 0; w < 32; ++w) { s1 += redA[w]; s2 += redB[w]; }
    const float vi1 = rsqrtf(s1 + EPSF);
    const float vi2 = rsqrtf(s2 + EPSF);

    // ---- epilogue ----
    const float INV32 = 1.0f / 32.0f;
    const float TWO_LN32 = 6.931471805599453f;

#pragma unroll
    for (int mf = 0; mf < 2; ++mf) {
        const int rbase = t0 + wm * 32 + mf * 16 + (lane >> 2);
#pragma unroll
        for (int n8 = 0; n8 < 2; ++n8) {
            const int col = s0 + wn * 16 + n8 * 8 + (lane & 3) * 2;
            const float* c1 = acc1[mf][n8];
            const float* c2 = acc2[mf][n8];
            float2 o0, o1;
            o0.x = -(TWO_LN32 + lg1p(vi1 * c1[0] * INV32) + lg1p(vi2 * c2[0] * INV32));
            o0.y = -(TWO_LN32 + lg1p(vi1 * c1[1] * INV32) + lg1p(vi2 * c2[1] * INV32));
            o1.x = -(TWO_LN32 + lg1p(vi1 * c1[2] * INV32) + lg1p(vi2 * c2[2] * INV32));
            o1.y = -(TWO_LN32 + lg1p(vi1 * c1[3] * INV32) + lg1p(vi2 * c2[3] * INV32));
            *(float2*)&out[((size_t)(i * TT + rbase)) * TT + col] = o0;
            *(float2*)&out[((size_t)(i * TT + rbase + 8)) * TT + col] = o1;
        }
    }
}

// ============================================================
extern "C" void kernel_launch(void* const* d_in, const int* in_sizes, int n_in,
                              void* d_out, int out_size) {
    // metadata order: pre_VF, pre_AF, back_VF, back_AF (only back_* are used)
    const float* VF = (const float*)d_in[2];
    const float* AF = (const float*)d_in[3];
    float* out = (float*)d_out;
    (void)in_sizes; (void)n_in; (void)out_size;

    cudaFuncSetAttribute(main_kernel,
                         cudaFuncAttributeMaxDynamicSharedMemorySize, SMEM_BYTES);

    stats1_kernel<<<512, 256>>>(VF, AF);
    build_kernel<<<dim3(256, 2), 256>>>(VF, AF);
    main_kernel<<<dim3(2, 2, 32), 1024, SMEM_BYTES>>>(out);
}